// round 2
// baseline (speedup 1.0000x reference)
#include <cuda_runtime.h>
#include <math.h>

#define BATCH 64
#define NPG 9
#define NTOT (BATCH*NPG)     // 576
#define H 128
#define K1 1801
#define O1 900
#define O2 100
#define ASL 243
#define KSPLIT 8
#define KCHUNK 226           // 7*226 + 219 = 1801

// scratch (no allocation allowed)
__device__ float g_s1_part[KSPLIT * BATCH * O1];
__device__ float g_Ai[NTOT * H];
__device__ float g_Bj[NTOT * H];
__device__ float g_D[BATCH * H];

// ---------------- GEMM1: s1_part = specs @ W1 (split-K) ----------------
// grid (29, 8), block 256. Block computes all 64 batches x 32 outs over one K chunk.
__global__ void gemm1_kernel(const float* __restrict__ spec, const float* __restrict__ W1) {
    const int t = threadIdx.x;
    const int o = blockIdx.x * 32 + (t & 31);
    const int bg = t >> 5;                 // 0..7 -> batches bg*8 .. bg*8+7
    const int kbeg = blockIdx.y * KCHUNK;
    const int kend = min(kbeg + KCHUNK, K1);

    __shared__ float sp[64 * 68];          // [batch][kk], stride 68 (16B aligned)
    float acc[8];
#pragma unroll
    for (int n = 0; n < 8; n++) acc[n] = 0.f;

    for (int k0 = kbeg; k0 < kend; k0 += 64) {
        const int klen = min(64, kend - k0);
        __syncthreads();
        for (int idx = t; idx < 64 * 64; idx += 256) {
            int bb = idx >> 6, kk = idx & 63;
            sp[bb * 68 + kk] = (kk < klen) ? spec[bb * K1 + k0 + kk] : 0.f;
        }
        __syncthreads();
        const float* spb = sp + bg * 8 * 68;
        int kk = 0;
        for (; kk + 4 <= klen; kk += 4) {
            float w0 = 0.f, w1 = 0.f, w2 = 0.f, w3 = 0.f;
            if (o < O1) {
                w0 = W1[(k0 + kk + 0) * O1 + o];
                w1 = W1[(k0 + kk + 1) * O1 + o];
                w2 = W1[(k0 + kk + 2) * O1 + o];
                w3 = W1[(k0 + kk + 3) * O1 + o];
            }
#pragma unroll
            for (int n = 0; n < 8; n++) {
                float4 sv = *(const float4*)(spb + n * 68 + kk);
                acc[n] += sv.x * w0 + sv.y * w1 + sv.z * w2 + sv.w * w3;
            }
        }
        for (; kk < klen; kk++) {
            float w = (o < O1) ? W1[(k0 + kk) * O1 + o] : 0.f;
#pragma unroll
            for (int n = 0; n < 8; n++) acc[n] += spb[n * 68 + kk] * w;
        }
    }
    if (o < O1) {
        float* dst = &g_s1_part[blockIdx.y * (BATCH * O1)];
#pragma unroll
        for (int n = 0; n < 8; n++)
            dst[(bg * 8 + n) * O1 + o] = acc[n];
    }
}

// ---------------- AB GEMM: [Ai | Bj] = relu(nf)[576,128] @ W[128,256] ----------------
// grid (18 m-tiles of 32, 4 n-tiles of 64), block 256, 8 outs/thread.
__global__ void ab_gemm_kernel(const float* __restrict__ nf, const float* __restrict__ Wa2) {
    __shared__ float As[32][128];   // relu(nf) tile, K fully resident
    __shared__ float Bs[128][64];   // weight tile
    const int t = threadIdx.x;
    const int m0 = blockIdx.x * 32;
    const int n0 = blockIdx.y * 64;
    // cols >= 128 come from Wa2 rows [128,256): offset = 128*128 - 128
    const int woff = (blockIdx.y >= 2) ? (H * H - H) : 0;

    for (int idx = t; idx < 32 * 128; idx += 256) {
        int r = idx >> 7, k = idx & 127;
        As[r][k] = fmaxf(nf[(m0 + r) * H + k], 0.f);
    }
    for (int idx = t; idx < 128 * 64; idx += 256) {
        int k = idx >> 6, c = idx & 63;
        Bs[k][c] = Wa2[k * H + n0 + c + woff];
    }
    __syncthreads();

    const int c = t & 63, r0 = t >> 6;   // r0 in 0..3, rows r0+4i
    float acc[8];
#pragma unroll
    for (int i = 0; i < 8; i++) acc[i] = 0.f;

    for (int k = 0; k < 128; k += 4) {
        float b0 = Bs[k][c], b1 = Bs[k + 1][c], b2 = Bs[k + 2][c], b3 = Bs[k + 3][c];
#pragma unroll
        for (int i = 0; i < 8; i++) {
            float4 a = *(const float4*)&As[r0 + 4 * i][k];
            acc[i] += a.x * b0 + a.y * b1 + a.z * b2 + a.w * b3;
        }
    }
    float* dst = (blockIdx.y < 2) ? g_Ai : g_Bj;
    const int col = (blockIdx.y < 2) ? (n0 + c) : (n0 - 128 + c);
#pragma unroll
    for (int i = 0; i < 8; i++)
        dst[(m0 + r0 + 4 * i) * H + col] = acc[i];
}

// ---------------- fused: reduce split-K -> gemm2 -> D -> value head ----------------
// grid 64 (one per graph), block 256
__global__ void mid_kernel(const float* __restrict__ nf,
                           const float* __restrict__ b1,
                           const float* __restrict__ W2, const float* __restrict__ b2,
                           const float* __restrict__ Wa2,
                           const float* __restrict__ Wv1, const float* __restrict__ bv1,
                           const float* __restrict__ Wv2, const float* __restrict__ bv2,
                           float* __restrict__ out) {
    const int b = blockIdx.x, t = threadIdx.x;
    __shared__ float sr[O1];
    __shared__ float ss2[2][O2];
    __shared__ float ss[O2];
    __shared__ float x[H + O2];
    __shared__ float hred[64];

    // split-K reduce + bias + relu
    for (int k = t; k < O1; k += 256) {
        float a = b1[k];
#pragma unroll
        for (int c = 0; c < KSPLIT; c++) a += g_s1_part[c * (BATCH * O1) + b * O1 + k];
        sr[k] = fmaxf(a, 0.f);
    }
    __syncthreads();

    // gemm2: 200 threads, 2-way K split for MLP
    if (t < 200) {
        const int o = t % O2, half = t / O2;
        float a = 0.f;
#pragma unroll 8
        for (int k = half; k < O1; k += 2) a += sr[k] * W2[k * O2 + o];
        ss2[half][o] = a;
    }
    __syncthreads();
    if (t < O2) ss[t] = fmaxf(ss2[0][t] + ss2[1][t] + b2[t], 0.f);
    __syncthreads();

    // D = s @ Wa2[256:356]
    if (t < H) {
        float d = 0.f;
#pragma unroll 4
        for (int k = 0; k < O2; k++) d += ss[k] * Wa2[(2 * H + k) * H + t];
        g_D[b * H + t] = d;
    }
    // value: readout (sum over 9 nodes) + spec concat
    if (t < H) {
        float sum = 0.f;
#pragma unroll
        for (int i = 0; i < NPG; i++) sum += nf[(b * NPG + i) * H + t];
        x[t] = sum;
    }
    if (t >= H && t < H + O2) x[t] = ss[t - H];
    __syncthreads();
    if (t < 64) {
        float a = bv1[t];
#pragma unroll 4
        for (int k = 0; k < H + O2; k++) a += x[k] * Wv1[k * 64 + t];
        hred[t] = fmaxf(a, 0.f) * Wv2[t];
    }
    __syncthreads();
    if (t == 0) {
        float v = bv2[0];
#pragma unroll
        for (int k = 0; k < 64; k++) v += hred[k];
        out[BATCH * ASL + b] = v;
    }
}

// ---------------- pair head + gather + softmax ----------------
// grid 64, block 256: one thread per (pair, bond) output element
__global__ void pair_kernel(const float* __restrict__ ba2, const float* __restrict__ Wf,
                            const float* __restrict__ bf, const int* __restrict__ indexmask,
                            const float* __restrict__ mask, float* __restrict__ out) {
    const int b = blockIdx.x, t = threadIdx.x;
    const int lane = t & 31, w = t >> 5;
    __shared__ float As[NPG * 132], Bs[NPG * 132], Dc[132];
    __shared__ float Wfs[H * 3];
    __shared__ float fp[ASL];
    __shared__ float red[8];
    __shared__ float rmax, rsum;

    for (int idx = t; idx < NPG * H; idx += 256) {
        int i = idx >> 7, h = idx & 127;
        As[i * 132 + h] = g_Ai[(b * NPG + i) * H + h];
        Bs[i * 132 + h] = g_Bj[(b * NPG + i) * H + h];
    }
    if (t < H) Dc[t] = g_D[b * H + t] + ba2[t];
    for (int idx = t; idx < H * 3; idx += 256) Wfs[idx] = Wf[idx];
    __syncthreads();

    if (t < ASL) {
        const int pair = t / 3, bond = t - pair * 3;
        const int i = pair / NPG, j = pair - i * NPG;
        const float* Ap = As + i * 132;
        const float* Bp = Bs + j * 132;
        float a = 0.f;
#pragma unroll 4
        for (int h = 0; h < H; h++) {
            float hv = fmaxf(Ap[h] + Bp[h] + Dc[h], 0.f);
            a += hv * Wfs[h * 3 + bond];
        }
        fp[t] = a + bf[bond];
    }
    __syncthreads();

    // gather + softmax (243 elems, one per thread)
    float g = -INFINITY;
    if (t < ASL) g = fp[indexmask[b * ASL + t]] + mask[b * ASL + t];

    float v = g;
#pragma unroll
    for (int off = 16; off; off >>= 1) v = fmaxf(v, __shfl_xor_sync(0xffffffffu, v, off));
    if (lane == 0) red[w] = v;
    __syncthreads();
    if (t == 0) {
        float m = red[0];
#pragma unroll
        for (int i = 1; i < 8; i++) m = fmaxf(m, red[i]);
        rmax = m;
    }
    __syncthreads();
    float e = (t < ASL) ? __expf(g - rmax) : 0.f;
    v = e;
#pragma unroll
    for (int off = 16; off; off >>= 1) v += __shfl_xor_sync(0xffffffffu, v, off);
    if (lane == 0) red[w] = v;
    __syncthreads();
    if (t == 0) {
        float s = 0.f;
#pragma unroll
        for (int i = 0; i < 8; i++) s += red[i];
        rsum = s;
    }
    __syncthreads();
    if (t < ASL) out[b * ASL + t] = e / rsum;
}

extern "C" void kernel_launch(void* const* d_in, const int* in_sizes, int n_in,
                              void* d_out, int out_size) {
    const float* nf   = (const float*)d_in[0];
    const float* spec = (const float*)d_in[1];
    // d_in[2] len_vec unused (block structure is known)
    const float* mask = (const float*)d_in[3];
    const int*   imask= (const int*)  d_in[4];
    const float* W1   = (const float*)d_in[5];
    const float* b1   = (const float*)d_in[6];
    const float* W2   = (const float*)d_in[7];
    const float* b2   = (const float*)d_in[8];
    const float* Wv1  = (const float*)d_in[9];
    const float* bv1  = (const float*)d_in[10];
    const float* Wv2  = (const float*)d_in[11];
    const float* bv2  = (const float*)d_in[12];
    const float* Wa2  = (const float*)d_in[13];
    const float* ba2  = (const float*)d_in[14];
    const float* Wf   = (const float*)d_in[15];
    const float* bf   = (const float*)d_in[16];
    float* out = (float*)d_out;

    gemm1_kernel<<<dim3((O1 + 31) / 32, KSPLIT), 256>>>(spec, W1);
    ab_gemm_kernel<<<dim3(NTOT / 32, 4), 256>>>(nf, Wa2);
    mid_kernel<<<BATCH, 256>>>(nf, b1, W2, b2, Wa2, Wv1, bv1, Wv2, bv2, out);
    pair_kernel<<<BATCH, 256>>>(ba2, Wf, bf, imask, mask, out);
}

// round 3
// speedup vs baseline: 1.1235x; 1.1235x over previous
#include <cuda_runtime.h>
#include <math.h>

#define NB 148
#define BATCH 64
#define NPG 9
#define NTOT (BATCH*NPG)   // 576
#define H 128
#define K1 1801
#define O1 900
#define O2 100
#define ASL 243
#define KS1 4
#define KC1 451            // 4*451 = 1804 >= 1801
#define KS2 16
#define KC2 57             // 16*57 = 912 >= 900

// scratch (no allocation allowed)
__device__ float g_s1_part[KS1 * BATCH * O1];
__device__ float g_s2_part[KS2 * BATCH * O2];
__device__ float g_Ai[NTOT * H];
__device__ float g_Bj[NTOT * H];
__device__ unsigned g_count = 0;
__device__ unsigned g_gen = 0;

__device__ __forceinline__ void grid_barrier() {
    __syncthreads();
    __threadfence();
    if (threadIdx.x == 0) {
        unsigned gen = *(volatile unsigned*)&g_gen;
        if (atomicAdd(&g_count, 1u) == NB - 1) {
            g_count = 0;            // ordered before gen bump by fence below
            __threadfence();
            atomicAdd(&g_gen, 1u);
        } else {
            while (*(volatile unsigned*)&g_gen == gen) __nanosleep(64);
        }
    }
    __syncthreads();
}

__global__ __launch_bounds__(256, 1)
void fused_kernel(const float* __restrict__ nf, const float* __restrict__ spec,
                  const float* __restrict__ mask, const int* __restrict__ imask,
                  const float* __restrict__ W1, const float* __restrict__ b1,
                  const float* __restrict__ W2, const float* __restrict__ b2,
                  const float* __restrict__ Wv1, const float* __restrict__ bv1,
                  const float* __restrict__ Wv2, const float* __restrict__ bv2,
                  const float* __restrict__ Wa2, const float* __restrict__ ba2,
                  const float* __restrict__ Wf, const float* __restrict__ bf,
                  float* __restrict__ out) {
    __shared__ __align__(16) float buf[12288];   // 48KB, reused per phase
    const int t = threadIdx.x;
    const int bid = blockIdx.x;

    // ================= Phase 1: gemm1 (116 blocks) + ab gemm (32 blocks) ==========
    if (bid < 116) {
        // s1_part[ks] = spec[64,1801-chunk] @ W1-chunk  (32 outs, all 64 batches)
        const int nt = bid >> 2, ks = bid & 3;
        const int lane = t & 31, bg = t >> 5;
        const int o = nt * 32 + lane;
        const int kbeg = ks * KC1;
        const int kend = min(kbeg + KC1, K1);
        float* sp = buf;               // [64][68]
        float* wt = buf + 64 * 68;     // [32][68]
        float acc[8];
#pragma unroll
        for (int n = 0; n < 8; n++) acc[n] = 0.f;

        for (int k0 = kbeg; k0 < kend; k0 += 64) {
            const int klen = min(64, kend - k0);
            __syncthreads();
            for (int idx = t; idx < 4096; idx += 256) {
                int bb = idx >> 6, kk = idx & 63;
                sp[bb * 68 + kk] = (kk < klen) ? spec[bb * K1 + k0 + kk] : 0.f;
            }
            for (int idx = t; idx < 2048; idx += 256) {
                int kk = idx >> 5, ol = idx & 31;
                int go = nt * 32 + ol;
                wt[ol * 68 + kk] = (kk < klen && go < O1) ? W1[(k0 + kk) * O1 + go] : 0.f;
            }
            __syncthreads();
            const float* spb = sp + bg * 8 * 68;
            const float* wrow = wt + lane * 68;
#pragma unroll 4
            for (int kk = 0; kk < 64; kk += 4) {
                float4 w4 = *(const float4*)(wrow + kk);
#pragma unroll
                for (int n = 0; n < 8; n++) {
                    float4 s4 = *(const float4*)(spb + n * 68 + kk);
                    acc[n] += s4.x * w4.x + s4.y * w4.y + s4.z * w4.z + s4.w * w4.w;
                }
            }
        }
        if (o < O1) {
#pragma unroll
            for (int n = 0; n < 8; n++)
                g_s1_part[ks * (BATCH * O1) + (bg * 8 + n) * O1 + o] = acc[n];
        }
    } else {
        // [Ai | Bj] = relu(nf)[576,128] @ Wa2[0:256 rows]; 72 tasks over 32 blocks
        float (*As)[128] = (float (*)[128])buf;            // 32x128
        float (*Bs)[64]  = (float (*)[64])(buf + 4096);    // 128x64
        for (int task = bid - 116; task < 72; task += 32) {
            const int mt = task % 18, nty = task / 18;
            const int m0 = mt * 32;
            const int n0 = nty * 64;
            const int woff = (nty >= 2) ? (H * H - H) : 0;
            __syncthreads();
            for (int idx = t; idx < 32 * 128; idx += 256) {
                int r = idx >> 7, k = idx & 127;
                As[r][k] = fmaxf(nf[(m0 + r) * H + k], 0.f);
            }
            for (int idx = t; idx < 128 * 64; idx += 256) {
                int k = idx >> 6, c = idx & 63;
                Bs[k][c] = Wa2[k * H + n0 + c + woff];
            }
            __syncthreads();
            const int c = t & 63, r0 = t >> 6;
            float acc[8];
#pragma unroll
            for (int i = 0; i < 8; i++) acc[i] = 0.f;
#pragma unroll 4
            for (int k = 0; k < 128; k += 4) {
                float b0 = Bs[k][c], b1v = Bs[k + 1][c], b2v = Bs[k + 2][c], b3 = Bs[k + 3][c];
#pragma unroll
                for (int i = 0; i < 8; i++) {
                    float4 a = *(const float4*)&As[r0 + 4 * i][k];
                    acc[i] += a.x * b0 + a.y * b1v + a.z * b2v + a.w * b3;
                }
            }
            float* dst = (nty < 2) ? g_Ai : g_Bj;
            const int col = (nty < 2) ? (n0 + c) : (n0 - 128 + c);
#pragma unroll
            for (int i = 0; i < 8; i++)
                dst[(m0 + r0 + 4 * i) * H + col] = acc[i];
        }
    }

    grid_barrier();

    // ================= Phase 2: reduce(gemm1) -> gemm2 split-K (64 blocks) =========
    if (bid < 64) {
        const int nt = bid & 3, ks = bid >> 2;       // nt: 4 o-tiles of 32, ks: 16 k-splits
        const int lane = t & 31, bg = t >> 5;
        const int o = nt * 32 + lane;
        const int kbeg = ks * KC2;
        const int kend = min(kbeg + KC2, O1);
        const int klen = kend - kbeg;
        float* s1r = buf;                            // [64][60]
        for (int idx = t; idx < 64 * KC2; idx += 256) {
            int b = idx / KC2, kk = idx - b * KC2;
            int gk = kbeg + kk;
            float v = 0.f;
            if (kk < klen) {
                v = b1[gk];
#pragma unroll
                for (int c = 0; c < KS1; c++)
                    v += g_s1_part[c * (BATCH * O1) + b * O1 + gk];
                v = fmaxf(v, 0.f);
            }
            s1r[b * 60 + kk] = v;
        }
        __syncthreads();
        float acc[8];
#pragma unroll
        for (int n = 0; n < 8; n++) acc[n] = 0.f;
        const float* sb = s1r + bg * 8 * 60;
#pragma unroll 4
        for (int kk = 0; kk < klen; kk++) {
            float w = (o < O2) ? W2[(kbeg + kk) * O2 + o] : 0.f;
#pragma unroll
            for (int n = 0; n < 8; n++)
                acc[n] += sb[n * 60 + kk] * w;
        }
        if (o < O2) {
#pragma unroll
            for (int n = 0; n < 8; n++)
                g_s2_part[ks * (BATCH * O2) + (bg * 8 + n) * O2 + o] = acc[n];
        }
    }

    grid_barrier();

    // ================= Phase 3: per-graph ss -> D -> value -> pair -> softmax ======
    if (bid < 64) {
        const int b = bid;
        const int lane = t & 31, w = t >> 5;
        float* ss  = buf;            // 100
        float* Dc  = buf + 128;      // 128
        float* x   = buf + 256;      // 228
        float* hred= buf + 512;      // 64
        float* As  = buf + 640;      // 9*132
        float* Bs  = buf + 1856;     // 9*132
        float* Wft = buf + 3072;     // 3*128 (bond-major)
        float* fp  = buf + 3456;     // 243
        float* red = buf + 3712;     // 8
        float* rs  = buf + 3724;     // rmax, rsum

        // ss = relu(b2 + sum_ks s2_part)
        if (t < O2) {
            float a = b2[t];
#pragma unroll
            for (int c = 0; c < KS2; c++)
                a += g_s2_part[c * (BATCH * O2) + b * O2 + t];
            ss[t] = fmaxf(a, 0.f);
        }
        __syncthreads();

        // Dc = D + ba2 ; x = [readout | ss] ; stage As/Bs/Wft
        if (t < H) {
            float d = ba2[t];
#pragma unroll 4
            for (int k = 0; k < O2; k++)
                d += ss[k] * Wa2[(2 * H + k) * H + t];
            Dc[t] = d;
            float sum = 0.f;
#pragma unroll
            for (int i = 0; i < NPG; i++) sum += nf[(b * NPG + i) * H + t];
            x[t] = sum;
        }
        if (t >= H && t < H + O2) x[t] = ss[t - H];
        for (int idx = t; idx < NPG * H; idx += 256) {
            int i = idx >> 7, h = idx & 127;
            As[i * 132 + h] = g_Ai[(b * NPG + i) * H + h];
            Bs[i * 132 + h] = g_Bj[(b * NPG + i) * H + h];
        }
        for (int idx = t; idx < H * 3; idx += 256)
            Wft[(idx % 3) * H + idx / 3] = Wf[idx];
        __syncthreads();

        // value hidden + pair logits
        if (t < 64) {
            float a = bv1[t];
#pragma unroll 4
            for (int k = 0; k < H + O2; k++) a += x[k] * Wv1[k * 64 + t];
            hred[t] = fmaxf(a, 0.f) * Wv2[t];
        }
        if (t < ASL) {
            const int pair = t / 3, bond = t - pair * 3;
            const int i = pair / NPG, j = pair - i * NPG;
            const float4* Ap = (const float4*)(As + i * 132);
            const float4* Bp = (const float4*)(Bs + j * 132);
            const float4* Dp = (const float4*)Dc;
            const float4* Wp = (const float4*)(Wft + bond * H);
            float a = 0.f;
#pragma unroll 8
            for (int q = 0; q < 32; q++) {
                float4 av = Ap[q], bv = Bp[q], dv = Dp[q], wv = Wp[q];
                a += fmaxf(av.x + bv.x + dv.x, 0.f) * wv.x
                   + fmaxf(av.y + bv.y + dv.y, 0.f) * wv.y
                   + fmaxf(av.z + bv.z + dv.z, 0.f) * wv.z
                   + fmaxf(av.w + bv.w + dv.w, 0.f) * wv.w;
            }
            fp[t] = a + bf[bond];
        }
        __syncthreads();

        // gather + softmax
        float g = -INFINITY;
        if (t < ASL) g = fp[imask[b * ASL + t]] + mask[b * ASL + t];
        float v = g;
#pragma unroll
        for (int off = 16; off; off >>= 1) v = fmaxf(v, __shfl_xor_sync(0xffffffffu, v, off));
        if (lane == 0) red[w] = v;
        __syncthreads();
        if (t == 0) {
            float m = red[0];
#pragma unroll
            for (int i = 1; i < 8; i++) m = fmaxf(m, red[i]);
            rs[0] = m;
        }
        __syncthreads();
        float e = (t < ASL) ? __expf(g - rs[0]) : 0.f;
        v = e;
#pragma unroll
        for (int off = 16; off; off >>= 1) v += __shfl_xor_sync(0xffffffffu, v, off);
        if (lane == 0) red[w] = v;
        __syncthreads();
        if (t == 0) {
            float s = 0.f;
#pragma unroll
            for (int i = 0; i < 8; i++) s += red[i];
            rs[1] = s;
            // value output
            float vo = bv2[0];
#pragma unroll
            for (int k = 0; k < 64; k++) vo += hred[k];
            out[BATCH * ASL + b] = vo;
        }
        __syncthreads();
        if (t < ASL) out[b * ASL + t] = e / rs[1];
    }
}

extern "C" void kernel_launch(void* const* d_in, const int* in_sizes, int n_in,
                              void* d_out, int out_size) {
    const float* nf   = (const float*)d_in[0];
    const float* spec = (const float*)d_in[1];
    // d_in[2] len_vec unused (block structure is known)
    const float* mask = (const float*)d_in[3];
    const int*   imask= (const int*)  d_in[4];
    const float* W1   = (const float*)d_in[5];
    const float* b1   = (const float*)d_in[6];
    const float* W2   = (const float*)d_in[7];
    const float* b2   = (const float*)d_in[8];
    const float* Wv1  = (const float*)d_in[9];
    const float* bv1  = (const float*)d_in[10];
    const float* Wv2  = (const float*)d_in[11];
    const float* bv2  = (const float*)d_in[12];
    const float* Wa2  = (const float*)d_in[13];
    const float* ba2  = (const float*)d_in[14];
    const float* Wf   = (const float*)d_in[15];
    const float* bf   = (const float*)d_in[16];
    float* out = (float*)d_out;

    fused_kernel<<<NB, 256>>>(nf, spec, mask, imask, W1, b1, W2, b2,
                              Wv1, bv1, Wv2, bv2, Wa2, ba2, Wf, bf, out);
}

// round 4
// speedup vs baseline: 1.2618x; 1.1231x over previous
#include <cuda_runtime.h>
#include <math.h>

#define NB 148
#define THREADS 512
#define BATCH 64
#define NPG 9
#define NTOT (BATCH*NPG)   // 576
#define H 128
#define K1 1801
#define O1 900
#define O2 100
#define ASL 243
#define KS1 8
#define KC1 226            // 7*226 + 219 = 1801
#define KS2 16
#define KC2 57             // 16*57 = 912 >= 900

// scratch (no allocation allowed)
__device__ float g_s1_part[KS1 * BATCH * O1];
__device__ float g_s2_part[KS2 * BATCH * O2];
__device__ float g_Ai[NTOT * H];
__device__ float g_Bj[NTOT * H];
__device__ unsigned g_count = 0;
__device__ unsigned g_gen = 0;

__device__ __forceinline__ void grid_barrier() {
    __syncthreads();
    __threadfence();
    if (threadIdx.x == 0) {
        unsigned gen = *(volatile unsigned*)&g_gen;
        if (atomicAdd(&g_count, 1u) == NB - 1) {
            g_count = 0;
            __threadfence();
            atomicAdd(&g_gen, 1u);
        } else {
            while (*(volatile unsigned*)&g_gen == gen) __nanosleep(64);
        }
    }
    __syncthreads();
}

__global__ __launch_bounds__(THREADS, 1)
void fused_kernel(const float* __restrict__ nf, const float* __restrict__ spec,
                  const float* __restrict__ mask, const int* __restrict__ imask,
                  const float* __restrict__ W1, const float* __restrict__ b1,
                  const float* __restrict__ W2, const float* __restrict__ b2,
                  const float* __restrict__ Wv1, const float* __restrict__ bv1,
                  const float* __restrict__ Wv2, const float* __restrict__ bv2,
                  const float* __restrict__ Wa2, const float* __restrict__ ba2,
                  const float* __restrict__ Wf, const float* __restrict__ bf,
                  float* __restrict__ out) {
    __shared__ __align__(16) float buf[12288];   // 48KB, reused per phase
    const int t = threadIdx.x;
    const int bid = blockIdx.x;

    // ========== Phase 1: gemm1 (120 blocks) + ab gemm (28 blocks) ==========
    if (bid < 120) {
        // spec[64,1801] @ W1[1801,900] -> s1_part[ks][64][900-tile]
        // block: 64 batches x 64 outs, k-split ks. Thread: 4 batches x 2 outs.
        const int nt = bid >> 3, ks = bid & 7;
        const int og = t & 31;               // out pair index
        const int bg = t >> 5;               // batch group (0..15), 4 batches
        const int o0 = nt * 64 + og * 2;
        const int b0 = bg * 4;
        const int kbeg = ks * KC1;
        const int kend = min(kbeg + KC1, K1);
        float* sp = buf;                     // [32][68] k-major spec tile
        float* wt = buf + 32 * 68;           // [32][68] k-major weight tile
        float a00 = 0.f, a01 = 0.f, a10 = 0.f, a11 = 0.f;
        float a20 = 0.f, a21 = 0.f, a30 = 0.f, a31 = 0.f;

        for (int k0 = kbeg; k0 < kend; k0 += 32) {
            const int klen = kend - k0;      // >=1, pad to 32 with zeros
            __syncthreads();
            for (int idx = t; idx < 2048; idx += THREADS) {
                int kk = idx & 31, bb = idx >> 5;
                sp[kk * 68 + bb] = (kk < klen) ? spec[bb * K1 + k0 + kk] : 0.f;
            }
            for (int idx = t; idx < 2048; idx += THREADS) {
                int kk = idx >> 6, oo = idx & 63;
                int o = nt * 64 + oo;
                wt[kk * 68 + oo] = (kk < klen && o < O1) ? W1[(k0 + kk) * O1 + o] : 0.f;
            }
            __syncthreads();
#pragma unroll
            for (int kk = 0; kk < 32; kk++) {
                float4 s4 = *(const float4*)(sp + kk * 68 + b0);
                float2 w2 = *(const float2*)(wt + kk * 68 + og * 2);
                a00 += s4.x * w2.x; a01 += s4.x * w2.y;
                a10 += s4.y * w2.x; a11 += s4.y * w2.y;
                a20 += s4.z * w2.x; a21 += s4.z * w2.y;
                a30 += s4.w * w2.x; a31 += s4.w * w2.y;
            }
        }
        float* dst = g_s1_part + ks * (BATCH * O1);
        if (o0 + 1 < O1) {
            dst[(b0 + 0) * O1 + o0] = a00; dst[(b0 + 0) * O1 + o0 + 1] = a01;
            dst[(b0 + 1) * O1 + o0] = a10; dst[(b0 + 1) * O1 + o0 + 1] = a11;
            dst[(b0 + 2) * O1 + o0] = a20; dst[(b0 + 2) * O1 + o0 + 1] = a21;
            dst[(b0 + 3) * O1 + o0] = a30; dst[(b0 + 3) * O1 + o0 + 1] = a31;
        } else if (o0 < O1) {
            dst[(b0 + 0) * O1 + o0] = a00;
            dst[(b0 + 1) * O1 + o0] = a10;
            dst[(b0 + 2) * O1 + o0] = a20;
            dst[(b0 + 3) * O1 + o0] = a30;
        }
    } else {
        // [Ai | Bj] = relu(nf)[576,128] @ Wa2[0:256]; 72 tasks over 28 blocks
        float (*As)[128] = (float (*)[128])buf;            // 32x128 (16KB)
        float (*Bs)[64]  = (float (*)[64])(buf + 4096);    // 128x64 (32KB)
        for (int task = bid - 120; task < 72; task += 28) {
            const int mt = task % 18, nty = task / 18;
            const int m0 = mt * 32;
            const int n0 = nty * 64;
            const int woff = (nty >= 2) ? (H * H - H) : 0;
            __syncthreads();
            for (int idx = t; idx < 32 * 128; idx += THREADS) {
                int r = idx >> 7, k = idx & 127;
                As[r][k] = fmaxf(nf[(m0 + r) * H + k], 0.f);
            }
            for (int idx = t; idx < 128 * 64; idx += THREADS) {
                int k = idx >> 6, c = idx & 63;
                Bs[k][c] = Wa2[k * H + n0 + c + woff];
            }
            __syncthreads();
            const int c = t & 63, r0 = t >> 6;   // 8 row groups, rows r0+8i
            float acc[4];
#pragma unroll
            for (int i = 0; i < 4; i++) acc[i] = 0.f;
#pragma unroll 8
            for (int k = 0; k < 128; k += 4) {
                float b0v = Bs[k][c], b1v = Bs[k + 1][c];
                float b2v = Bs[k + 2][c], b3v = Bs[k + 3][c];
#pragma unroll
                for (int i = 0; i < 4; i++) {
                    float4 a = *(const float4*)&As[r0 + 8 * i][k];
                    acc[i] += a.x * b0v + a.y * b1v + a.z * b2v + a.w * b3v;
                }
            }
            float* dst = (nty < 2) ? g_Ai : g_Bj;
            const int col = (nty < 2) ? (n0 + c) : (n0 - 128 + c);
#pragma unroll
            for (int i = 0; i < 4; i++)
                dst[(m0 + r0 + 8 * i) * H + col] = acc[i];
        }
    }

    grid_barrier();

    // ========== Phase 2: reduce(gemm1) -> gemm2 split-K (64 blocks) ==========
    if (bid < 64) {
        const int nt = bid & 3, ks = bid >> 2;   // 4 o-tiles x 16 k-splits
        const int o = nt * 32 + (t & 31);
        const int bg = t >> 5;                    // 0..15, 4 batches each
        const int b0 = bg * 4;
        const int kbeg = ks * KC2;
        const int kend = min(kbeg + KC2, O1);
        const int klen = kend - kbeg;
        float* s1r = buf;                         // [64][60]
        for (int idx = t; idx < 64 * KC2; idx += THREADS) {
            int b = idx / KC2, kk = idx - b * KC2;
            float v = 0.f;
            if (kk < klen) {
                int gk = kbeg + kk;
                v = b1[gk];
#pragma unroll
                for (int c = 0; c < KS1; c++)
                    v += g_s1_part[c * (BATCH * O1) + b * O1 + gk];
                v = fmaxf(v, 0.f);
            }
            s1r[b * 60 + kk] = v;
        }
        __syncthreads();
        float acc[4] = {0.f, 0.f, 0.f, 0.f};
        const float* sb = s1r + b0 * 60;
        for (int kk = 0; kk < klen; kk++) {
            float w = (o < O2) ? W2[(kbeg + kk) * O2 + o] : 0.f;
            acc[0] += sb[kk] * w;
            acc[1] += sb[60 + kk] * w;
            acc[2] += sb[120 + kk] * w;
            acc[3] += sb[180 + kk] * w;
        }
        if (o < O2) {
#pragma unroll
            for (int n = 0; n < 4; n++)
                g_s2_part[ks * (BATCH * O2) + (b0 + n) * O2 + o] = acc[n];
        }
    }

    grid_barrier();

    // ========== Phase 3: per-graph ss -> D -> value -> pair -> softmax ==========
    if (bid < 64) {
        const int b = bid;
        const int lane = t & 31, w = t >> 5;
        float* ss  = buf;            // 100
        float* Dc  = buf + 128;      // 128
        float* x   = buf + 256;      // 228
        float* hred= buf + 512;      // 64
        float* As  = buf + 640;      // 9*132
        float* Bs  = buf + 1856;     // 9*132
        float* Wft = buf + 3072;     // 3*128 (bond-major)
        float* fp  = buf + 3456;     // 243
        float* red = buf + 3712;     // 16
        float* rs  = buf + 3744;     // rmax, rsum

        if (t < O2) {
            float a = b2[t];
#pragma unroll
            for (int c = 0; c < KS2; c++)
                a += g_s2_part[c * (BATCH * O2) + b * O2 + t];
            ss[t] = fmaxf(a, 0.f);
        }
        __syncthreads();

        if (t < H) {
            float d = ba2[t];
#pragma unroll 4
            for (int k = 0; k < O2; k++)
                d += ss[k] * Wa2[(2 * H + k) * H + t];
            Dc[t] = d;
            float sum = 0.f;
#pragma unroll
            for (int i = 0; i < NPG; i++) sum += nf[(b * NPG + i) * H + t];
            x[t] = sum;
        }
        if (t >= H && t < H + O2) x[t] = ss[t - H];
        for (int idx = t; idx < NPG * H; idx += THREADS) {
            int i = idx >> 7, h = idx & 127;
            As[i * 132 + h] = g_Ai[(b * NPG + i) * H + h];
            Bs[i * 132 + h] = g_Bj[(b * NPG + i) * H + h];
        }
        for (int idx = t; idx < H * 3; idx += THREADS)
            Wft[(idx % 3) * H + idx / 3] = Wf[idx];
        __syncthreads();

        if (t < 64) {
            float a = bv1[t];
#pragma unroll 4
            for (int k = 0; k < H + O2; k++) a += x[k] * Wv1[k * 64 + t];
            hred[t] = fmaxf(a, 0.f) * Wv2[t];
        }
        if (t < ASL) {
            const int pair = t / 3, bond = t - pair * 3;
            const int i = pair / NPG, j = pair - i * NPG;
            const float4* Ap = (const float4*)(As + i * 132);
            const float4* Bp = (const float4*)(Bs + j * 132);
            const float4* Dp = (const float4*)Dc;
            const float4* Wp = (const float4*)(Wft + bond * H);
            float a = 0.f;
#pragma unroll 8
            for (int q = 0; q < 32; q++) {
                float4 av = Ap[q], bv = Bp[q], dv = Dp[q], wv = Wp[q];
                a += fmaxf(av.x + bv.x + dv.x, 0.f) * wv.x
                   + fmaxf(av.y + bv.y + dv.y, 0.f) * wv.y
                   + fmaxf(av.z + bv.z + dv.z, 0.f) * wv.z
                   + fmaxf(av.w + bv.w + dv.w, 0.f) * wv.w;
            }
            fp[t] = a + bf[bond];
        }
        __syncthreads();

        float g = -INFINITY;
        if (t < ASL) g = fp[imask[b * ASL + t]] + mask[b * ASL + t];
        float v = g;
#pragma unroll
        for (int off = 16; off; off >>= 1) v = fmaxf(v, __shfl_xor_sync(0xffffffffu, v, off));
        if (lane == 0) red[w] = v;
        __syncthreads();
        if (t == 0) {
            float m = red[0];
#pragma unroll
            for (int i = 1; i < 16; i++) m = fmaxf(m, red[i]);
            rs[0] = m;
        }
        __syncthreads();
        float e = (t < ASL) ? __expf(g - rs[0]) : 0.f;
        v = e;
#pragma unroll
        for (int off = 16; off; off >>= 1) v += __shfl_xor_sync(0xffffffffu, v, off);
        if (lane == 0) red[w] = v;
        __syncthreads();
        if (t == 0) {
            float s = 0.f;
#pragma unroll
            for (int i = 0; i < 16; i++) s += red[i];
            rs[1] = s;
            float vo = bv2[0];
#pragma unroll
            for (int k = 0; k < 64; k++) vo += hred[k];
            out[BATCH * ASL + b] = vo;
        }
        __syncthreads();
        if (t < ASL) out[b * ASL + t] = e / rs[1];
    }
}

extern "C" void kernel_launch(void* const* d_in, const int* in_sizes, int n_in,
                              void* d_out, int out_size) {
    const float* nf   = (const float*)d_in[0];
    const float* spec = (const float*)d_in[1];
    const float* mask = (const float*)d_in[3];
    const int*   imask= (const int*)  d_in[4];
    const float* W1   = (const float*)d_in[5];
    const float* b1   = (const float*)d_in[6];
    const float* W2   = (const float*)d_in[7];
    const float* b2   = (const float*)d_in[8];
    const float* Wv1  = (const float*)d_in[9];
    const float* bv1  = (const float*)d_in[10];
    const float* Wv2  = (const float*)d_in[11];
    const float* bv2  = (const float*)d_in[12];
    const float* Wa2  = (const float*)d_in[13];
    const float* ba2  = (const float*)d_in[14];
    const float* Wf   = (const float*)d_in[15];
    const float* bf   = (const float*)d_in[16];
    float* out = (float*)d_out;

    fused_kernel<<<NB, THREADS>>>(nf, spec, mask, imask, W1, b1, W2, b2,
                                  Wv1, bv1, Wv2, bv2, Wa2, ba2, Wf, bf, out);
}

// round 5
// speedup vs baseline: 1.5330x; 1.2149x over previous
#include <cuda_runtime.h>
#include <math.h>

#define NB 148
#define THREADS 512
#define BATCH 64
#define NPG 9
#define NTOT (BATCH*NPG)   // 576
#define H 128
#define K1 1801
#define O1 900
#define O2 100
#define ASL 243
#define NT1 15             // 15 n-tiles x 64 outs (last partially masked)
#define KS1 9
#define KC1 201            // 9*201 = 1809 >= 1801
#define KS2 16
#define KC2 57             // 16*57 = 912 >= 900

// scratch (no allocation allowed)
__device__ float g_s1_part[KS1 * BATCH * O1];
__device__ float g_s2_part[KS2 * BATCH * O2];
__device__ float g_Ai[NTOT * H];
__device__ float g_Bj[NTOT * H];
__device__ unsigned g_count = 0;
__device__ unsigned g_gen = 0;

__device__ __forceinline__ void grid_barrier() {
    __syncthreads();
    __threadfence();
    if (threadIdx.x == 0) {
        unsigned gen = *(volatile unsigned*)&g_gen;
        if (atomicAdd(&g_count, 1u) == NB - 1) {
            g_count = 0;
            __threadfence();
            atomicAdd(&g_gen, 1u);
        } else {
            while (*(volatile unsigned*)&g_gen == gen) __nanosleep(32);
        }
    }
    __syncthreads();
}

// One 32-row x 64-col tile of [Ai|Bj] = relu(nf) @ Wa2[0:256 rows]
__device__ __forceinline__ void ab_task(int task, int t, float* buf,
                                        const float* __restrict__ nf,
                                        const float* __restrict__ Wa2) {
    float (*As)[128] = (float (*)[128])buf;            // 32x128
    float (*Bs)[64]  = (float (*)[64])(buf + 4096);    // 128x64
    const int mt = task % 18, nty = task / 18;
    const int m0 = mt * 32;
    const int n0 = nty * 64;
    const int woff = (nty >= 2) ? (H * H - H) : 0;
    for (int idx = t; idx < 32 * 128; idx += THREADS) {
        int r = idx >> 7, k = idx & 127;
        As[r][k] = fmaxf(nf[(m0 + r) * H + k], 0.f);
    }
    for (int idx = t; idx < 128 * 64; idx += THREADS) {
        int k = idx >> 6, c = idx & 63;
        Bs[k][c] = Wa2[k * H + n0 + c + woff];
    }
    __syncthreads();
    const int c = t & 63, r0 = t >> 6;   // 8 row groups, rows r0+8i
    float acc[4] = {0.f, 0.f, 0.f, 0.f};
#pragma unroll 8
    for (int k = 0; k < 128; k += 4) {
        float b0v = Bs[k][c], b1v = Bs[k + 1][c];
        float b2v = Bs[k + 2][c], b3v = Bs[k + 3][c];
#pragma unroll
        for (int i = 0; i < 4; i++) {
            float4 a = *(const float4*)&As[r0 + 8 * i][k];
            acc[i] += a.x * b0v + a.y * b1v + a.z * b2v + a.w * b3v;
        }
    }
    float* dst = (nty < 2) ? g_Ai : g_Bj;
    const int col = (nty < 2) ? (n0 + c) : (n0 - 128 + c);
#pragma unroll
    for (int i = 0; i < 4; i++)
        dst[(m0 + r0 + 8 * i) * H + col] = acc[i];
}

__global__ __launch_bounds__(THREADS, 1)
void fused_kernel(const float* __restrict__ nf, const float* __restrict__ spec,
                  const float* __restrict__ mask, const int* __restrict__ imask,
                  const float* __restrict__ W1, const float* __restrict__ b1,
                  const float* __restrict__ W2, const float* __restrict__ b2,
                  const float* __restrict__ Wv1, const float* __restrict__ bv1,
                  const float* __restrict__ Wv2, const float* __restrict__ bv2,
                  const float* __restrict__ Wa2, const float* __restrict__ ba2,
                  const float* __restrict__ Wf, const float* __restrict__ bf,
                  float* __restrict__ out) {
    __shared__ __align__(16) float buf[12288];   // 48KB, reused per phase
    const int t = threadIdx.x;
    const int bid = blockIdx.x;

    // ========== Phase 1: gemm1 (135 blocks, reg-prefetch) + 13 ab tasks ==========
    if (bid < NT1 * KS1) {
        const int nt = bid / KS1, ks = bid % KS1;
        const int og = t & 31;               // out-pair index
        const int bg = t >> 5;               // batch group (0..15), 4 batches
        const int o0 = nt * 64 + og * 2;
        const int b0 = bg * 4;
        const int kbeg = ks * KC1;
        const int kend = min(kbeg + KC1, K1);
        const int nch = (kend - kbeg + 31) >> 5;
        float* sp = buf;                     // [32][68] k-major spec tile
        float* wt = buf + 32 * 68;           // [32][68] k-major weight tile

        // fixed staging coords per thread
        const int kk_s = t & 31;             // spec k within chunk
        const int bb_s = t >> 5;             // spec batch base (+16j)
        const int kk_w = t >> 6;             // weight k base (+8j)
        const int oo_w = t & 63;
        const int ow_g = nt * 64 + oo_w;
        const bool wok = (ow_g < O1);

        float rs[4], rw[4];
        {   // prefetch chunk 0
            const int k0 = kbeg;
            const int klen = kend - k0;
#pragma unroll
            for (int j = 0; j < 4; j++)
                rs[j] = (kk_s < klen) ? spec[(bb_s + 16 * j) * K1 + k0 + kk_s] : 0.f;
#pragma unroll
            for (int j = 0; j < 4; j++) {
                int kk = kk_w + 8 * j;
                rw[j] = (kk < klen && wok) ? W1[(k0 + kk) * O1 + ow_g] : 0.f;
            }
        }
        float a00 = 0.f, a01 = 0.f, a10 = 0.f, a11 = 0.f;
        float a20 = 0.f, a21 = 0.f, a30 = 0.f, a31 = 0.f;

        for (int c = 0; c < nch; c++) {
            __syncthreads();
#pragma unroll
            for (int j = 0; j < 4; j++)
                sp[kk_s * 68 + bb_s + 16 * j] = rs[j];
#pragma unroll
            for (int j = 0; j < 4; j++)
                wt[(kk_w + 8 * j) * 68 + oo_w] = rw[j];
            __syncthreads();
            if (c + 1 < nch) {   // prefetch next chunk while computing
                const int k0 = kbeg + (c + 1) * 32;
                const int klen = kend - k0;
#pragma unroll
                for (int j = 0; j < 4; j++)
                    rs[j] = (kk_s < klen) ? spec[(bb_s + 16 * j) * K1 + k0 + kk_s] : 0.f;
#pragma unroll
                for (int j = 0; j < 4; j++) {
                    int kk = kk_w + 8 * j;
                    rw[j] = (kk < klen && wok) ? W1[(k0 + kk) * O1 + ow_g] : 0.f;
                }
            }
#pragma unroll
            for (int kk = 0; kk < 32; kk++) {
                float4 s4 = *(const float4*)(sp + kk * 68 + b0);
                float2 w2 = *(const float2*)(wt + kk * 68 + og * 2);
                a00 += s4.x * w2.x; a01 += s4.x * w2.y;
                a10 += s4.y * w2.x; a11 += s4.y * w2.y;
                a20 += s4.z * w2.x; a21 += s4.z * w2.y;
                a30 += s4.w * w2.x; a31 += s4.w * w2.y;
            }
        }
        float* dst = g_s1_part + ks * (BATCH * O1);
        if (o0 + 1 < O1) {
            dst[(b0 + 0) * O1 + o0] = a00; dst[(b0 + 0) * O1 + o0 + 1] = a01;
            dst[(b0 + 1) * O1 + o0] = a10; dst[(b0 + 1) * O1 + o0 + 1] = a11;
            dst[(b0 + 2) * O1 + o0] = a20; dst[(b0 + 2) * O1 + o0 + 1] = a21;
            dst[(b0 + 3) * O1 + o0] = a30; dst[(b0 + 3) * O1 + o0 + 1] = a31;
        } else if (o0 < O1) {
            dst[(b0 + 0) * O1 + o0] = a00;
            dst[(b0 + 1) * O1 + o0] = a10;
            dst[(b0 + 2) * O1 + o0] = a20;
            dst[(b0 + 3) * O1 + o0] = a30;
        }
    } else {
        ab_task(bid - NT1 * KS1, t, buf, nf, Wa2);   // tasks 0..12
    }

    grid_barrier();

    // ========== Phase 2: gemm2 (blocks 0-63) + ab tasks 13-71 (blocks 64-122) =====
    if (bid < 64) {
        const int nt = bid & 3, ks = bid >> 2;   // 4 o-tiles x 16 k-splits
        const int o = nt * 32 + (t & 31);
        const int bg = t >> 5;
        const int b0 = bg * 4;
        const int kbeg = ks * KC2;
        const int kend = min(kbeg + KC2, O1);
        const int klen = kend - kbeg;
        float* s1r = buf;                         // [64][60]
        for (int idx = t; idx < 64 * KC2; idx += THREADS) {
            int b = idx / KC2, kk = idx - b * KC2;
            float v = 0.f;
            if (kk < klen) {
                int gk = kbeg + kk;
                v = b1[gk];
#pragma unroll
                for (int c = 0; c < KS1; c++)
                    v += g_s1_part[c * (BATCH * O1) + b * O1 + gk];
                v = fmaxf(v, 0.f);
            }
            s1r[b * 60 + kk] = v;
        }
        __syncthreads();
        float acc[4] = {0.f, 0.f, 0.f, 0.f};
        const float* sb = s1r + b0 * 60;
        for (int kk = 0; kk < klen; kk++) {
            float w = (o < O2) ? W2[(kbeg + kk) * O2 + o] : 0.f;
            acc[0] += sb[kk] * w;
            acc[1] += sb[60 + kk] * w;
            acc[2] += sb[120 + kk] * w;
            acc[3] += sb[180 + kk] * w;
        }
        if (o < O2) {
#pragma unroll
            for (int n = 0; n < 4; n++)
                g_s2_part[ks * (BATCH * O2) + (b0 + n) * O2 + o] = acc[n];
        }
    } else if (bid < 64 + 59) {
        ab_task(13 + (bid - 64), t, buf, nf, Wa2);   // tasks 13..71
    }

    grid_barrier();

    // ========== Phase 3: per-graph ss -> D -> value -> pair -> softmax ==========
    if (bid < 64) {
        const int b = bid;
        const int lane = t & 31, w = t >> 5;
        float* ss  = buf;            // 100
        float* Dc  = buf + 128;      // 128
        float* x   = buf + 256;      // 228
        float* hred= buf + 512;      // 64
        float* As  = buf + 640;      // 9*132
        float* Bs  = buf + 1856;     // 9*132
        float* Wft = buf + 3072;     // 3*128 (bond-major)
        float* fp  = buf + 3456;     // 243
        float* red = buf + 3712;     // 16
        float* rs2 = buf + 3744;     // rmax, rsum

        if (t < O2) {
            float a = b2[t];
#pragma unroll
            for (int c = 0; c < KS2; c++)
                a += g_s2_part[c * (BATCH * O2) + b * O2 + t];
            ss[t] = fmaxf(a, 0.f);
        }
        __syncthreads();

        if (t < H) {
            float d = ba2[t];
#pragma unroll 4
            for (int k = 0; k < O2; k++)
                d += ss[k] * Wa2[(2 * H + k) * H + t];
            Dc[t] = d;
            float sum = 0.f;
#pragma unroll
            for (int i = 0; i < NPG; i++) sum += nf[(b * NPG + i) * H + t];
            x[t] = sum;
        }
        if (t >= H && t < H + O2) x[t] = ss[t - H];
        for (int idx = t; idx < NPG * H; idx += THREADS) {
            int i = idx >> 7, h = idx & 127;
            As[i * 132 + h] = g_Ai[(b * NPG + i) * H + h];
            Bs[i * 132 + h] = g_Bj[(b * NPG + i) * H + h];
        }
        for (int idx = t; idx < H * 3; idx += THREADS)
            Wft[(idx % 3) * H + idx / 3] = Wf[idx];
        __syncthreads();

        if (t < 64) {
            float a = bv1[t];
#pragma unroll 4
            for (int k = 0; k < H + O2; k++) a += x[k] * Wv1[k * 64 + t];
            hred[t] = fmaxf(a, 0.f) * Wv2[t];
        }
        if (t < ASL) {
            const int pair = t / 3, bond = t - pair * 3;
            const int i = pair / NPG, j = pair - i * NPG;
            const float4* Ap = (const float4*)(As + i * 132);
            const float4* Bp = (const float4*)(Bs + j * 132);
            const float4* Dp = (const float4*)Dc;
            const float4* Wp = (const float4*)(Wft + bond * H);
            float a = 0.f;
#pragma unroll 8
            for (int q = 0; q < 32; q++) {
                float4 av = Ap[q], bv = Bp[q], dv = Dp[q], wv = Wp[q];
                a += fmaxf(av.x + bv.x + dv.x, 0.f) * wv.x
                   + fmaxf(av.y + bv.y + dv.y, 0.f) * wv.y
                   + fmaxf(av.z + bv.z + dv.z, 0.f) * wv.z
                   + fmaxf(av.w + bv.w + dv.w, 0.f) * wv.w;
            }
            fp[t] = a + bf[bond];
        }
        __syncthreads();

        float g = -INFINITY;
        if (t < ASL) g = fp[imask[b * ASL + t]] + mask[b * ASL + t];
        float v = g;
#pragma unroll
        for (int off = 16; off; off >>= 1) v = fmaxf(v, __shfl_xor_sync(0xffffffffu, v, off));
        if (lane == 0) red[w] = v;
        __syncthreads();
        if (t == 0) {
            float m = red[0];
#pragma unroll
            for (int i = 1; i < 16; i++) m = fmaxf(m, red[i]);
            rs2[0] = m;
        }
        __syncthreads();
        float e = (t < ASL) ? __expf(g - rs2[0]) : 0.f;
        v = e;
#pragma unroll
        for (int off = 16; off; off >>= 1) v += __shfl_xor_sync(0xffffffffu, v, off);
        if (lane == 0) red[w] = v;
        __syncthreads();
        if (t == 0) {
            float s = 0.f;
#pragma unroll
            for (int i = 0; i < 16; i++) s += red[i];
            rs2[1] = s;
            float vo = bv2[0];
#pragma unroll
            for (int k = 0; k < 64; k++) vo += hred[k];
            out[BATCH * ASL + b] = vo;
        }
        __syncthreads();
        if (t < ASL) out[b * ASL + t] = e / rs2[1];
    }
}

extern "C" void kernel_launch(void* const* d_in, const int* in_sizes, int n_in,
                              void* d_out, int out_size) {
    const float* nf   = (const float*)d_in[0];
    const float* spec = (const float*)d_in[1];
    const float* mask = (const float*)d_in[3];
    const int*   imask= (const int*)  d_in[4];
    const float* W1   = (const float*)d_in[5];
    const float* b1   = (const float*)d_in[6];
    const float* W2   = (const float*)d_in[7];
    const float* b2   = (const float*)d_in[8];
    const float* Wv1  = (const float*)d_in[9];
    const float* bv1  = (const float*)d_in[10];
    const float* Wv2  = (const float*)d_in[11];
    const float* bv2  = (const float*)d_in[12];
    const float* Wa2  = (const float*)d_in[13];
    const float* ba2  = (const float*)d_in[14];
    const float* Wf   = (const float*)d_in[15];
    const float* bf   = (const float*)d_in[16];
    float* out = (float*)d_out;

    fused_kernel<<<NB, THREADS>>>(nf, spec, mask, imask, W1, b1, W2, b2,
                                  Wv1, bv1, Wv2, bv2, Wa2, ba2, Wf, bf, out);
}